// round 6
// baseline (speedup 1.0000x reference)
#include <cuda_runtime.h>
#include <cuda_bf16.h>

#define BB   64
#define TT   512
#define II   256
#define HH   1024
#define G4   4096
#define HOR  24
#define NCTA 128
#define WP   1032          // smem weight pitch in floats (bank-conflict-free, 16B aligned)
#define CHUNK 64

// ---- scratch (device globals; allocation-free) ----
__device__ float g_xg[(size_t)TT * G4 * BB];   // [T][4H][B]
__device__ float g_h1[(size_t)TT * HH * BB];   // [T][H][B]
__device__ float g_h2[2 * HH * BB];            // ping-pong [H][B]
__device__ float g_c [HH * BB];                // cell state [H][B]
__device__ int   g_bar[TT];                    // per-step barrier counters

typedef unsigned long long u64;

__device__ __forceinline__ u64 pack2(float lo, float hi) {
    u64 r; asm("mov.b64 %0, {%1, %2};" : "=l"(r) : "f"(lo), "f"(hi)); return r;
}
__device__ __forceinline__ void unpack2(u64 v, float& lo, float& hi) {
    asm("mov.b64 {%0, %1}, %2;" : "=f"(lo), "=f"(hi) : "l"(v));
}
__device__ __forceinline__ void fma2(u64& d, u64 a, u64 b) {
    asm("fma.rn.f32x2 %0, %1, %2, %0;" : "+l"(d) : "l"(a), "l"(b));
}
__device__ __forceinline__ float sigm(float x) { return 1.0f / (1.0f + __expf(-x)); }

// ---- zero cell state + barrier counters ----
__global__ void zero_state() {
    int i = blockIdx.x * blockDim.x + threadIdx.x;
    if (i < HH * BB) g_c[i] = 0.0f;
    if (i < TT) g_bar[i] = 0;
}

// ---- input projection: g_xg[t][j][b] = sum_k A(t,b,k)*W[j][k] + bih[j]+bhh[j]
// mode 0: A = x[b][t][k], K=II.  mode 1: A = g_h1[t][k][b], K=HH.
__global__ __launch_bounds__(256) void gemm_xg(
    const float* __restrict__ X, const float* __restrict__ W,
    const float* __restrict__ bih, const float* __restrict__ bhh, int mode)
{
    __shared__ float sA[16 * 72];
    __shared__ u64   sW[16 * 66];
    __shared__ float sBias[64];

    const int tid = threadIdx.x;
    const int t   = blockIdx.y;
    const int j0  = blockIdx.x * 64;
    const int K   = mode ? HH : II;

    if (tid < 64) sBias[tid] = bih[j0 + tid] + bhh[j0 + tid];
    __syncthreads();

    const int txb = tid & 15;
    const int tyj = tid >> 4;

    u64 acc[4][2];
    #pragma unroll
    for (int j = 0; j < 4; j++) {
        float bj = sBias[tyj * 4 + j];
        acc[j][0] = pack2(bj, bj);
        acc[j][1] = pack2(bj, bj);
    }

    for (int k0 = 0; k0 < K; k0 += 16) {
        __syncthreads();
        if (mode == 0) {
            int b = tid >> 2, kq = tid & 3;
            float4 v = *(const float4*)(X + ((size_t)(b * TT + t)) * II + k0 + kq * 4);
            sA[(kq * 4 + 0) * 72 + b] = v.x;
            sA[(kq * 4 + 1) * 72 + b] = v.y;
            sA[(kq * 4 + 2) * 72 + b] = v.z;
            sA[(kq * 4 + 3) * 72 + b] = v.w;
        } else {
            int kk = tid >> 4, b4 = tid & 15;
            float4 v = *(const float4*)(g_h1 + ((size_t)t * HH + k0 + kk) * BB + b4 * 4);
            *(float4*)(sA + kk * 72 + b4 * 4) = v;
        }
        {
            int j = tid >> 2, kq = tid & 3;
            float4 w = *(const float4*)(W + (size_t)(j0 + j) * K + k0 + kq * 4);
            sW[(kq * 4 + 0) * 66 + j] = pack2(w.x, w.x);
            sW[(kq * 4 + 1) * 66 + j] = pack2(w.y, w.y);
            sW[(kq * 4 + 2) * 66 + j] = pack2(w.z, w.z);
            sW[(kq * 4 + 3) * 66 + j] = pack2(w.w, w.w);
        }
        __syncthreads();
        #pragma unroll
        for (int kk = 0; kk < 16; kk++) {
            longlong2 a   = ((const longlong2*)(sA + kk * 72))[txb];
            longlong2 w01 = ((const longlong2*)(sW + kk * 66))[tyj * 2];
            longlong2 w23 = ((const longlong2*)(sW + kk * 66))[tyj * 2 + 1];
            u64 a01 = (u64)a.x, a23 = (u64)a.y;
            fma2(acc[0][0], a01, (u64)w01.x); fma2(acc[0][1], a23, (u64)w01.x);
            fma2(acc[1][0], a01, (u64)w01.y); fma2(acc[1][1], a23, (u64)w01.y);
            fma2(acc[2][0], a01, (u64)w23.x); fma2(acc[2][1], a23, (u64)w23.x);
            fma2(acc[3][0], a01, (u64)w23.y); fma2(acc[3][1], a23, (u64)w23.y);
        }
    }
    #pragma unroll
    for (int j = 0; j < 4; j++) {
        float4 o;
        unpack2(acc[j][0], o.x, o.y);
        unpack2(acc[j][1], o.z, o.w);
        *(float4*)(g_xg + ((size_t)t * G4 + j0 + tyj * 4 + j) * BB + txb * 4) = o;
    }
}

// ---- persistent LSTM layer kernel ----
// 128 CTAs (<=148 SMs -> all co-resident). CTA cb owns h-cols cb*8..+7 (x4 gates).
// Whh slice (32 cols x 1024 k, 132 KB) resident in smem for all 512 steps.
// Per-step global sync via g_bar[t].
__global__ __launch_bounds__(256) void lstm_layer_kernel(const float* __restrict__ Whh, int layer)
{
    extern __shared__ float smem[];
    float* sWf = smem;                       // 32*WP floats
    float* sHA = smem + 32 * WP;             // CHUNK*64
    float* sHB = sHA + CHUNK * 64;           // CHUNK*64
    float* sG  = sHB + CHUNK * 64;           // 32*65

    const int tid = threadIdx.x;
    const int cb  = blockIdx.x;
    const int tx  = tid & 7;
    const int ty  = tid >> 3;
    const int jcol = (ty >> 3) * HH + cb * 8 + (ty & 7);

    // Load Whh slice once: col c (0..31) -> global row (c>>3)*HH + cb*8 + (c&7)
    for (int i = tid; i < 32 * 256; i += 256) {
        int c  = i >> 8;
        int k4 = i & 255;
        int j  = (c >> 3) * HH + cb * 8 + (c & 7);
        float4 w = *(const float4*)(Whh + (size_t)j * HH + k4 * 4);
        *(float4*)(sWf + c * WP + k4 * 4) = w;
    }
    __syncthreads();

    for (int t = 0; t < TT; t++) {
        const float* xg = g_xg + (size_t)t * G4 * BB;
        const float* hprev;
        float* hout;
        if (layer == 0) {
            hprev = g_h1 + (size_t)(t > 0 ? t - 1 : 0) * HH * BB;
            hout  = g_h1 + (size_t)t * HH * BB;
        } else {
            hprev = g_h2 + (size_t)((t - 1) & 1) * HH * BB;
            hout  = g_h2 + (size_t)(t & 1) * HH * BB;
        }

        u64 acc[4] = {0ull, 0ull, 0ull, 0ull};

        if (t > 0) {
            // prefetch chunk 0 (L2-coherent loads: other SMs wrote hprev)
            float4 r[4];
            #pragma unroll
            for (int q = 0; q < 4; q++)
                r[q] = __ldcg((const float4*)hprev + q * 256 + tid);

            for (int c = 0; c < HH / CHUNK; c++) {
                float* buf = (c & 1) ? sHB : sHA;
                #pragma unroll
                for (int q = 0; q < 4; q++)
                    *(float4*)(buf + (q * 256 + tid) * 4) = r[q];
                __syncthreads();
                if (c + 1 < HH / CHUNK) {
                    const float* src = hprev + (c + 1) * CHUNK * BB;
                    #pragma unroll
                    for (int q = 0; q < 4; q++)
                        r[q] = __ldcg((const float4*)src + q * 256 + tid);
                }
                const float* wrow = sWf + ty * WP + c * CHUNK;
                #pragma unroll
                for (int k4 = 0; k4 < CHUNK; k4 += 4) {
                    // front-load all LDS for 4 k's, then 16 FFMA2
                    float w0 = wrow[k4], w1 = wrow[k4 + 1], w2 = wrow[k4 + 2], w3 = wrow[k4 + 3];
                    const longlong2* h0 = (const longlong2*)(buf + (k4 + 0) * 64);
                    const longlong2* h1 = (const longlong2*)(buf + (k4 + 1) * 64);
                    const longlong2* h2 = (const longlong2*)(buf + (k4 + 2) * 64);
                    const longlong2* h3 = (const longlong2*)(buf + (k4 + 3) * 64);
                    longlong2 a0 = h0[tx * 2], b0 = h0[tx * 2 + 1];
                    longlong2 a1 = h1[tx * 2], b1 = h1[tx * 2 + 1];
                    longlong2 a2 = h2[tx * 2], b2 = h2[tx * 2 + 1];
                    longlong2 a3 = h3[tx * 2], b3 = h3[tx * 2 + 1];
                    u64 p0 = pack2(w0, w0), p1 = pack2(w1, w1);
                    u64 p2 = pack2(w2, w2), p3 = pack2(w3, w3);
                    fma2(acc[0], (u64)a0.x, p0); fma2(acc[1], (u64)a0.y, p0);
                    fma2(acc[2], (u64)b0.x, p0); fma2(acc[3], (u64)b0.y, p0);
                    fma2(acc[0], (u64)a1.x, p1); fma2(acc[1], (u64)a1.y, p1);
                    fma2(acc[2], (u64)b1.x, p1); fma2(acc[3], (u64)b1.y, p1);
                    fma2(acc[0], (u64)a2.x, p2); fma2(acc[1], (u64)a2.y, p2);
                    fma2(acc[2], (u64)b2.x, p2); fma2(acc[3], (u64)b2.y, p2);
                    fma2(acc[0], (u64)a3.x, p3); fma2(acc[1], (u64)a3.y, p3);
                    fma2(acc[2], (u64)b3.x, p3); fma2(acc[3], (u64)b3.y, p3);
                }
                __syncthreads();
            }
        }

        // gates = acc + xg, exchange via smem
        {
            float4 x0 = *(const float4*)(xg + (size_t)jcol * BB + tx * 8);
            float4 x1 = *(const float4*)(xg + (size_t)jcol * BB + tx * 8 + 4);
            float v0, v1, v2, v3, v4, v5, v6, v7;
            unpack2(acc[0], v0, v1); unpack2(acc[1], v2, v3);
            unpack2(acc[2], v4, v5); unpack2(acc[3], v6, v7);
            float* g = sG + ty * 65 + tx * 8;
            g[0] = v0 + x0.x; g[1] = v1 + x0.y; g[2] = v2 + x0.z; g[3] = v3 + x0.w;
            g[4] = v4 + x1.x; g[5] = v5 + x1.y; g[6] = v6 + x1.z; g[7] = v7 + x1.w;
        }
        __syncthreads();

        // cell update: thread -> h-col cc, 2 batches
        {
            int cc = tid >> 5;
            int b2 = (tid & 31) * 2;
            int hidx = (cb * 8 + cc) * BB + b2;
            float2 cold = *(float2*)(g_c + hidx);
            float2 cnew, hnew;

            float ig = sigm(sG[(0  + cc) * 65 + b2]);
            float fg = sigm(sG[(8  + cc) * 65 + b2]);
            float gg = tanhf(sG[(16 + cc) * 65 + b2]);
            float og = sigm(sG[(24 + cc) * 65 + b2]);
            cnew.x = fg * cold.x + ig * gg;
            hnew.x = og * tanhf(cnew.x);

            ig = sigm(sG[(0  + cc) * 65 + b2 + 1]);
            fg = sigm(sG[(8  + cc) * 65 + b2 + 1]);
            gg = tanhf(sG[(16 + cc) * 65 + b2 + 1]);
            og = sigm(sG[(24 + cc) * 65 + b2 + 1]);
            cnew.y = fg * cold.y + ig * gg;
            hnew.y = og * tanhf(cnew.y);

            *(float2*)(g_c + hidx)  = cnew;
            *(float2*)(hout + hidx) = hnew;
        }

        // global barrier (skip after last step; launch boundary syncs)
        if (t < TT - 1) {
            __threadfence();
            __syncthreads();
            if (tid == 0) {
                atomicAdd(&g_bar[t], 1);
                while (*(volatile int*)(g_bar + t) < NCTA) { }
            }
            __syncthreads();
        }
    }
}

// ---- head: out[b][r] = sum_k h2_last[k][b] * Wh[r][k] + bh[r] ----
__global__ __launch_bounds__(128) void head_kernel(
    const float* __restrict__ Wh, const float* __restrict__ bh, float* __restrict__ out)
{
    __shared__ float red[4];
    const int r = blockIdx.x, b = blockIdx.y;
    const int tid = threadIdx.x;
    const float* h = g_h2 + (size_t)((TT - 1) & 1) * HH * BB;

    float s = 0.0f;
    for (int k = tid; k < HH; k += 128) s += h[(size_t)k * BB + b] * Wh[(size_t)r * HH + k];
    #pragma unroll
    for (int o = 16; o > 0; o >>= 1) s += __shfl_down_sync(0xFFFFFFFFu, s, o);
    if ((tid & 31) == 0) red[tid >> 5] = s;
    __syncthreads();
    if (tid == 0) out[b * HOR + r] = red[0] + red[1] + red[2] + red[3] + bh[r];
}

extern "C" void kernel_launch(void* const* d_in, const int* in_sizes, int n_in,
                              void* d_out, int out_size) {
    const float* x     = (const float*)d_in[0];
    const float* Wih0  = (const float*)d_in[1];
    const float* Whh0  = (const float*)d_in[2];
    const float* bih0  = (const float*)d_in[3];
    const float* bhh0  = (const float*)d_in[4];
    const float* Wih1  = (const float*)d_in[5];
    const float* Whh1  = (const float*)d_in[6];
    const float* bih1  = (const float*)d_in[7];
    const float* bhh1  = (const float*)d_in[8];
    const float* Whead = (const float*)d_in[9];
    const float* bhead = (const float*)d_in[10];
    float* out = (float*)d_out;

    const int SMEM = (32 * WP + 2 * CHUNK * 64 + 32 * 65) * (int)sizeof(float);
    static int configured = 0;
    if (!configured) {
        cudaFuncSetAttribute(lstm_layer_kernel,
                             cudaFuncAttributeMaxDynamicSharedMemorySize, SMEM);
        configured = 1;
    }

    // layer 0
    zero_state<<<(HH * BB + 255) / 256, 256>>>();
    gemm_xg<<<dim3(G4 / 64, TT), 256>>>(x, Wih0, bih0, bhh0, 0);
    lstm_layer_kernel<<<NCTA, 256, SMEM>>>(Whh0, 0);

    // layer 1
    zero_state<<<(HH * BB + 255) / 256, 256>>>();
    gemm_xg<<<dim3(G4 / 64, TT), 256>>>(x, Wih1, bih1, bhh1, 1);
    lstm_layer_kernel<<<NCTA, 256, SMEM>>>(Whh1, 1);

    // head
    head_kernel<<<dim3(HOR, BB), 128>>>(Whead, bhead, out);
}

// round 7
// speedup vs baseline: 3.1290x; 3.1290x over previous
#include <cuda_runtime.h>
#include <cuda_bf16.h>

#define BB   64
#define TT   512
#define II   256
#define HH   1024
#define G4   4096
#define HOR  24
#define NCTA 128

// ---- scratch (device globals; allocation-free) ----
__device__ float g_xg[(size_t)TT * G4 * BB];   // [T][4H][B]
__device__ float g_h1[(size_t)TT * HH * BB];   // [T][H][B]
__device__ float g_h2[2 * HH * BB];            // ping-pong [H][B]
__device__ float g_c [HH * BB];                // cell state [H][B]
__device__ int   g_bar[TT];                    // per-step barrier counters

typedef unsigned long long u64;

__device__ __forceinline__ u64 pack2(float lo, float hi) {
    u64 r; asm("mov.b64 %0, {%1, %2};" : "=l"(r) : "f"(lo), "f"(hi)); return r;
}
__device__ __forceinline__ void unpack2(u64 v, float& lo, float& hi) {
    asm("mov.b64 {%0, %1}, %2;" : "=f"(lo), "=f"(hi) : "l"(v));
}
__device__ __forceinline__ void fma2(u64& d, u64 a, u64 b) {
    asm("fma.rn.f32x2 %0, %1, %2, %0;" : "+l"(d) : "l"(a), "l"(b));
}
__device__ __forceinline__ float sigm(float x) { return 1.0f / (1.0f + __expf(-x)); }

// ---- zero cell state + barrier counters ----
__global__ void zero_state() {
    int i = blockIdx.x * blockDim.x + threadIdx.x;
    if (i < HH * BB) g_c[i] = 0.0f;
    if (i < TT) g_bar[i] = 0;
}

// ---- input projection GEMM ----
// g_xg[t][j][b] = sum_k A(t,b,k)*W[j][k] + bih[j]+bhh[j]
// mode 0: A = x[b][t][k], K=II.  mode 1: A = g_h1[t][k][b], K=HH.
// CTA: 128 j x 64 b, 128 threads, thread tile 8j x 8b (f32x2 pairs over batch).
__global__ __launch_bounds__(128) void gemm_xg(
    const float* __restrict__ X, const float* __restrict__ W,
    const float* __restrict__ bih, const float* __restrict__ bhh, int mode)
{
    __shared__ __align__(16) float sA[16 * 68];    // [kk][b]  pitch 68
    __shared__ __align__(16) float sWt[16 * 132];  // [kk][j]  pitch 132
    __shared__ float sBias[128];

    const int tid = threadIdx.x;
    const int t   = blockIdx.y;
    const int j0  = blockIdx.x * 128;
    const int K   = mode ? HH : II;
    const int jg  = tid & 15;        // j-group: cols jg*8..+7
    const int bg  = tid >> 4;        // b-group: batches bg*8..+7

    sBias[tid] = bih[j0 + tid] + bhh[j0 + tid];
    __syncthreads();

    u64 acc[32];
    #pragma unroll
    for (int jl = 0; jl < 8; jl++) {
        float bj = sBias[jg * 8 + jl];
        u64 p = pack2(bj, bj);
        acc[jl * 4 + 0] = p; acc[jl * 4 + 1] = p;
        acc[jl * 4 + 2] = p; acc[jl * 4 + 3] = p;
    }

    for (int k0 = 0; k0 < K; k0 += 16) {
        __syncthreads();
        // stage A [16k x 64b]
        if (mode == 0) {
            #pragma unroll
            for (int q = 0; q < 2; q++) {
                int f = q * 128 + tid;
                int b = f >> 2, kq = f & 3;
                float4 v = *(const float4*)(X + ((size_t)b * TT + t) * II + k0 + kq * 4);
                sA[(kq * 4 + 0) * 68 + b] = v.x;
                sA[(kq * 4 + 1) * 68 + b] = v.y;
                sA[(kq * 4 + 2) * 68 + b] = v.z;
                sA[(kq * 4 + 3) * 68 + b] = v.w;
            }
        } else {
            #pragma unroll
            for (int q = 0; q < 2; q++) {
                int f = q * 128 + tid;
                int kk = f >> 4, b4 = f & 15;
                float4 v = *(const float4*)(g_h1 + ((size_t)t * HH + k0 + kk) * BB + b4 * 4);
                *(float4*)(sA + kk * 68 + b4 * 4) = v;
            }
        }
        // stage W [16k x 128j] (transpose)
        #pragma unroll
        for (int q = 0; q < 4; q++) {
            int f = q * 128 + tid;
            int j = f >> 2, kq = f & 3;
            float4 v = *(const float4*)(W + (size_t)(j0 + j) * K + k0 + kq * 4);
            sWt[(kq * 4 + 0) * 132 + j] = v.x;
            sWt[(kq * 4 + 1) * 132 + j] = v.y;
            sWt[(kq * 4 + 2) * 132 + j] = v.z;
            sWt[(kq * 4 + 3) * 132 + j] = v.w;
        }
        __syncthreads();
        #pragma unroll
        for (int kk = 0; kk < 16; kk++) {
            longlong2 ha = *(const longlong2*)(sA + kk * 68 + bg * 8);
            longlong2 hb = *(const longlong2*)(sA + kk * 68 + bg * 8 + 4);
            float4 w0 = *(const float4*)(sWt + kk * 132 + jg * 8);
            float4 w1 = *(const float4*)(sWt + kk * 132 + jg * 8 + 4);
            u64 hq[4] = { (u64)ha.x, (u64)ha.y, (u64)hb.x, (u64)hb.y };
            u64 p[8]  = { pack2(w0.x, w0.x), pack2(w0.y, w0.y),
                          pack2(w0.z, w0.z), pack2(w0.w, w0.w),
                          pack2(w1.x, w1.x), pack2(w1.y, w1.y),
                          pack2(w1.z, w1.z), pack2(w1.w, w1.w) };
            #pragma unroll
            for (int jl = 0; jl < 8; jl++)
                #pragma unroll
                for (int bp = 0; bp < 4; bp++)
                    fma2(acc[jl * 4 + bp], hq[bp], p[jl]);
        }
    }
    #pragma unroll
    for (int jl = 0; jl < 8; jl++) {
        float* orow = g_xg + ((size_t)t * G4 + j0 + jg * 8 + jl) * BB + bg * 8;
        *(u64*)(orow + 0) = acc[jl * 4 + 0];
        *(u64*)(orow + 2) = acc[jl * 4 + 1];
        *(u64*)(orow + 4) = acc[jl * 4 + 2];
        *(u64*)(orow + 6) = acc[jl * 4 + 3];
    }
}

// ---- persistent LSTM layer kernel ----
// 128 CTAs (all co-resident). CTA cb owns h-cols cb*8..+7 x 4 gates = 32 gate cols x 64 b.
// Whh slice transposed [k][32c] resident in smem (128 KB). 8 warps = 8 k-split groups.
// Warp lane: cg=lane&3 (gate, 8 cols each), bg=lane>>2 (8 batches). 32 u64 accs/thread.
__global__ __launch_bounds__(256) void lstm_layer_kernel(const float* __restrict__ Whh, int layer)
{
    extern __shared__ float smem[];
    float* sW  = smem;               // [k][32] : 32768 floats
    float* sH0 = smem + 32768;       // chunk buf A: 8192 floats (8 kg x 16 kk x 64 b)
    float* sH1 = sH0 + 8192;         // chunk buf B
    float* sG  = sH1 + 8192;         // gates [32][65]

    const int tid  = threadIdx.x;
    const int cb   = blockIdx.x;
    const int kg   = tid >> 5;       // k-group (warp)
    const int lane = tid & 31;
    const int cg   = lane & 3;       // gate
    const int bg   = lane >> 2;      // batch group

    // one-time: load Whh slice transposed. sW[k*32 + c] = Whh[(c>>3)*HH + cb*8 + (c&7)][k]
    for (int i = tid; i < 32768; i += 256) {
        int k = i >> 5, c = i & 31;
        int j = (c >> 3) * HH + cb * 8 + (c & 7);
        sW[i] = Whh[(size_t)j * HH + k];
    }
    __syncthreads();

    for (int t = 0; t < TT; t++) {
        const float* xg = g_xg + (size_t)t * G4 * BB;
        const float* hprev;
        float* hout;
        if (layer == 0) {
            hprev = g_h1 + (size_t)(t > 0 ? t - 1 : 0) * HH * BB;
            hout  = g_h1 + (size_t)t * HH * BB;
        } else {
            hprev = g_h2 + (size_t)((t - 1) & 1) * HH * BB;
            hout  = g_h2 + (size_t)(t & 1) * HH * BB;
        }

        u64 acc[32];
        #pragma unroll
        for (int i = 0; i < 32; i++) acc[i] = 0ull;

        if (t > 0) {
            // chunk c covers, for each kg, k in [kg*128 + c*16, +16)
            float4 pf[8];
            #pragma unroll
            for (int q = 0; q < 8; q++) {
                int f = q * 256 + tid;
                int blk = f >> 8, r = f & 255;
                pf[q] = __ldcg((const float4*)hprev + blk * 2048 + r);
            }
            for (int c = 0; c < 8; c++) {
                float* buf = (c & 1) ? sH1 : sH0;
                #pragma unroll
                for (int q = 0; q < 8; q++)
                    *((float4*)buf + q * 256 + tid) = pf[q];
                __syncthreads();
                if (c < 7) {
                    #pragma unroll
                    for (int q = 0; q < 8; q++) {
                        int f = q * 256 + tid;
                        int blk = f >> 8, r = f & 255;
                        pf[q] = __ldcg((const float4*)hprev + blk * 2048 + (c + 1) * 256 + r);
                    }
                }
                const float* hb = buf + kg * 1024 + bg * 8;
                const float* wb = sW + (kg * 128 + c * 16) * 32 + cg * 8;
                #pragma unroll
                for (int kk = 0; kk < 16; kk++) {
                    longlong2 ha = *(const longlong2*)(hb + kk * 64);
                    longlong2 h2 = *(const longlong2*)(hb + kk * 64 + 4);
                    float4 w0 = *(const float4*)(wb + kk * 32);
                    float4 w1 = *(const float4*)(wb + kk * 32 + 4);
                    u64 hq[4] = { (u64)ha.x, (u64)ha.y, (u64)h2.x, (u64)h2.y };
                    u64 p[8]  = { pack2(w0.x, w0.x), pack2(w0.y, w0.y),
                                  pack2(w0.z, w0.z), pack2(w0.w, w0.w),
                                  pack2(w1.x, w1.x), pack2(w1.y, w1.y),
                                  pack2(w1.z, w1.z), pack2(w1.w, w1.w) };
                    #pragma unroll
                    for (int cl = 0; cl < 8; cl++)
                        #pragma unroll
                        for (int bp = 0; bp < 4; bp++)
                            fma2(acc[cl * 4 + bp], hq[bp], p[cl]);
                }
                __syncthreads();
            }
        }

        // unpack to floats, tree-reduce the 8 k-groups (rows padded to 68 floats)
        float f[64];
        #pragma unroll
        for (int i = 0; i < 32; i++) unpack2(acc[i], f[2 * i], f[2 * i + 1]);

        float* rbuf = sH0;  // reuse staging area (16384 floats available)
        for (int h = 4; h >= 1; h >>= 1) {
            __syncthreads();
            if (kg >= h && kg < 2 * h) {
                float* dst = rbuf + ((kg - h) * 32 + lane) * 68;
                #pragma unroll
                for (int i = 0; i < 64; i += 4)
                    *(float4*)(dst + i) = make_float4(f[i], f[i + 1], f[i + 2], f[i + 3]);
            }
            __syncthreads();
            if (kg < h) {
                const float* src = rbuf + (kg * 32 + lane) * 68;
                #pragma unroll
                for (int i = 0; i < 64; i += 4) {
                    float4 v = *(const float4*)(src + i);
                    f[i] += v.x; f[i + 1] += v.y; f[i + 2] += v.z; f[i + 3] += v.w;
                }
            }
        }

        // warp 0 holds totals: add xg, publish gates to sG
        if (kg == 0) {
            #pragma unroll
            for (int cl = 0; cl < 8; cl++) {
                int cc = cg * 8 + cl;                      // CTA gate-col (gate=cg, hcol=cl)
                int j  = cg * HH + cb * 8 + cl;            // global gate row
                const float* xr = xg + (size_t)j * BB + bg * 8;
                float4 x0 = *(const float4*)xr;
                float4 x1 = *(const float4*)(xr + 4);
                float* gd = sG + cc * 65 + bg * 8;
                gd[0] = f[cl * 8 + 0] + x0.x; gd[1] = f[cl * 8 + 1] + x0.y;
                gd[2] = f[cl * 8 + 2] + x0.z; gd[3] = f[cl * 8 + 3] + x0.w;
                gd[4] = f[cl * 8 + 4] + x1.x; gd[5] = f[cl * 8 + 5] + x1.y;
                gd[6] = f[cl * 8 + 6] + x1.z; gd[7] = f[cl * 8 + 7] + x1.w;
            }
        }
        __syncthreads();

        // cell update: thread -> h-col cc2, 2 batches
        {
            int cc2 = tid >> 5;
            int b2  = (tid & 31) * 2;
            int hidx = (cb * 8 + cc2) * BB + b2;
            float2 cold = *(float2*)(g_c + hidx);
            float2 cnew, hnew;

            float ig = sigm(sG[(0  + cc2) * 65 + b2]);
            float fg = sigm(sG[(8  + cc2) * 65 + b2]);
            float gg = tanhf(sG[(16 + cc2) * 65 + b2]);
            float og = sigm(sG[(24 + cc2) * 65 + b2]);
            cnew.x = fg * cold.x + ig * gg;
            hnew.x = og * tanhf(cnew.x);

            ig = sigm(sG[(0  + cc2) * 65 + b2 + 1]);
            fg = sigm(sG[(8  + cc2) * 65 + b2 + 1]);
            gg = tanhf(sG[(16 + cc2) * 65 + b2 + 1]);
            og = sigm(sG[(24 + cc2) * 65 + b2 + 1]);
            cnew.y = fg * cold.y + ig * gg;
            hnew.y = og * tanhf(cnew.y);

            *(float2*)(g_c + hidx)  = cnew;
            *(float2*)(hout + hidx) = hnew;
        }

        // global barrier (skip after last step)
        if (t < TT - 1) {
            __threadfence();
            __syncthreads();
            if (tid == 0) {
                atomicAdd(&g_bar[t], 1);
                while (*(volatile int*)(g_bar + t) < NCTA) { }
            }
            __syncthreads();
        }
    }
}

// ---- head: out[b][r] = sum_k h2_last[k][b] * Wh[r][k] + bh[r] ----
__global__ __launch_bounds__(128) void head_kernel(
    const float* __restrict__ Wh, const float* __restrict__ bh, float* __restrict__ out)
{
    __shared__ float red[4];
    const int r = blockIdx.x, b = blockIdx.y;
    const int tid = threadIdx.x;
    const float* h = g_h2 + (size_t)((TT - 1) & 1) * HH * BB;

    float s = 0.0f;
    for (int k = tid; k < HH; k += 128) s += h[(size_t)k * BB + b] * Wh[(size_t)r * HH + k];
    #pragma unroll
    for (int o = 16; o > 0; o >>= 1) s += __shfl_down_sync(0xFFFFFFFFu, s, o);
    if ((tid & 31) == 0) red[tid >> 5] = s;
    __syncthreads();
    if (tid == 0) out[b * HOR + r] = red[0] + red[1] + red[2] + red[3] + bh[r];
}

extern "C" void kernel_launch(void* const* d_in, const int* in_sizes, int n_in,
                              void* d_out, int out_size) {
    const float* x     = (const float*)d_in[0];
    const float* Wih0  = (const float*)d_in[1];
    const float* Whh0  = (const float*)d_in[2];
    const float* bih0  = (const float*)d_in[3];
    const float* bhh0  = (const float*)d_in[4];
    const float* Wih1  = (const float*)d_in[5];
    const float* Whh1  = (const float*)d_in[6];
    const float* bih1  = (const float*)d_in[7];
    const float* bhh1  = (const float*)d_in[8];
    const float* Whead = (const float*)d_in[9];
    const float* bhead = (const float*)d_in[10];
    float* out = (float*)d_out;

    const int SMEM = (32768 + 2 * 8192 + 32 * 65) * (int)sizeof(float);  // 204928 B
    static int configured = 0;
    if (!configured) {
        cudaFuncSetAttribute(lstm_layer_kernel,
                             cudaFuncAttributeMaxDynamicSharedMemorySize, SMEM);
        configured = 1;
    }

    // layer 0
    zero_state<<<(HH * BB + 255) / 256, 256>>>();
    gemm_xg<<<dim3(G4 / 128, TT), 128>>>(x, Wih0, bih0, bhh0, 0);
    lstm_layer_kernel<<<NCTA, 256, SMEM>>>(Whh0, 0);

    // layer 1
    zero_state<<<(HH * BB + 255) / 256, 256>>>();
    gemm_xg<<<dim3(G4 / 128, TT), 128>>>(x, Wih1, bih1, bhh1, 1);
    lstm_layer_kernel<<<NCTA, 256, SMEM>>>(Whh1, 1);

    // head
    head_kernel<<<dim3(HOR, BB), 128>>>(Whead, bhead, out);
}

// round 9
// speedup vs baseline: 4.0418x; 1.2917x over previous
#include <cuda_runtime.h>
#include <cuda_bf16.h>
#include <cstdint>

#define BB   64
#define TT   512
#define II   256
#define HH   1024
#define G4   4096
#define HOR  24
#define NCTA 128

typedef unsigned long long u64;

// ---- scratch (device globals; allocation-free) ----
__device__ float g_xg[(size_t)TT * G4 * BB];        // [T][4H][B]
__device__ float g_h1[(size_t)TT * HH * BB];        // [T][H][B] fp32 (layer0 history for gemm)
__device__ float g_h2[HH * BB];                     // layer1 final h [H][B]
__device__ __nv_bfloat16 g_hhi[2][(size_t)BB * HH]; // split h hi, ping-pong, [b][k]
__device__ __nv_bfloat16 g_hlo[2][(size_t)BB * HH]; // split h lo
__device__ int   g_bar[TT];

// ---- scalar helpers ----
__device__ __forceinline__ u64 pack2(float lo, float hi) {
    u64 r; asm("mov.b64 %0, {%1, %2};" : "=l"(r) : "f"(lo), "f"(hi)); return r;
}
__device__ __forceinline__ void unpack2(u64 v, float& lo, float& hi) {
    asm("mov.b64 {%0, %1}, %2;" : "=f"(lo), "=f"(hi) : "l"(v));
}
__device__ __forceinline__ void fma2(u64& d, u64 a, u64 b) {
    asm("fma.rn.f32x2 %0, %1, %2, %0;" : "+l"(d) : "l"(a), "l"(b));
}
__device__ __forceinline__ float sigm(float x) { return 1.0f / (1.0f + __expf(-x)); }

// m16n8k16 bf16 mma, D==C accumulate in place
__device__ __forceinline__ void mma16816(float* d, const uint32_t* a, const uint32_t* b) {
    asm volatile(
        "mma.sync.aligned.m16n8k16.row.col.f32.bf16.bf16.f32 "
        "{%0,%1,%2,%3}, {%4,%5,%6,%7}, {%8,%9}, {%0,%1,%2,%3};\n"
        : "+f"(d[0]), "+f"(d[1]), "+f"(d[2]), "+f"(d[3])
        : "r"(a[0]), "r"(a[1]), "r"(a[2]), "r"(a[3]), "r"(b[0]), "r"(b[1]));
}

// ---- smem layout (bytes) for lstm kernel ----
#define WPIT   1032                        // W smem pitch in bf16 elems (2064B, +4 banks/row)
#define HPIT   136                         // h chunk pitch in bf16 elems (272B)
#define SM_WHI 0
#define SM_WLO (32 * WPIT * 2)                      // 66048
#define SM_H   (SM_WLO + 32 * WPIT * 2)             // 132096; [2 buf][2 plane][64*HPIT*2B]
#define HPLANE (64 * HPIT * 2)                      // 17408
#define SM_RED (SM_H + 4 * HPLANE)                  // 201728; float[4][32][33]
#define SMEM_TC (SM_RED + 4 * 32 * 33 * 4)          // 218624

// ---- zero barrier counters ----
__global__ void zero_state() {
    int i = blockIdx.x * blockDim.x + threadIdx.x;
    if (i < TT) g_bar[i] = 0;
}

// ---- input projection GEMM (fp32 FFMA2, unchanged from passing R7) ----
__global__ __launch_bounds__(128) void gemm_xg(
    const float* __restrict__ X, const float* __restrict__ W,
    const float* __restrict__ bih, const float* __restrict__ bhh, int mode)
{
    __shared__ __align__(16) float sA[16 * 68];
    __shared__ __align__(16) float sWt[16 * 132];
    __shared__ float sBias[128];

    const int tid = threadIdx.x;
    const int t   = blockIdx.y;
    const int j0  = blockIdx.x * 128;
    const int K   = mode ? HH : II;
    const int jg  = tid & 15;
    const int bg  = tid >> 4;

    sBias[tid] = bih[j0 + tid] + bhh[j0 + tid];
    __syncthreads();

    u64 acc[32];
    #pragma unroll
    for (int jl = 0; jl < 8; jl++) {
        float bj = sBias[jg * 8 + jl];
        u64 p = pack2(bj, bj);
        acc[jl * 4 + 0] = p; acc[jl * 4 + 1] = p;
        acc[jl * 4 + 2] = p; acc[jl * 4 + 3] = p;
    }

    for (int k0 = 0; k0 < K; k0 += 16) {
        __syncthreads();
        if (mode == 0) {
            #pragma unroll
            for (int q = 0; q < 2; q++) {
                int f = q * 128 + tid;
                int b = f >> 2, kq = f & 3;
                float4 v = *(const float4*)(X + ((size_t)b * TT + t) * II + k0 + kq * 4);
                sA[(kq * 4 + 0) * 68 + b] = v.x;
                sA[(kq * 4 + 1) * 68 + b] = v.y;
                sA[(kq * 4 + 2) * 68 + b] = v.z;
                sA[(kq * 4 + 3) * 68 + b] = v.w;
            }
        } else {
            #pragma unroll
            for (int q = 0; q < 2; q++) {
                int f = q * 128 + tid;
                int kk = f >> 4, b4 = f & 15;
                float4 v = *(const float4*)(g_h1 + ((size_t)t * HH + k0 + kk) * BB + b4 * 4);
                *(float4*)(sA + kk * 68 + b4 * 4) = v;
            }
        }
        #pragma unroll
        for (int q = 0; q < 4; q++) {
            int f = q * 128 + tid;
            int j = f >> 2, kq = f & 3;
            float4 v = *(const float4*)(W + (size_t)(j0 + j) * K + k0 + kq * 4);
            sWt[(kq * 4 + 0) * 132 + j] = v.x;
            sWt[(kq * 4 + 1) * 132 + j] = v.y;
            sWt[(kq * 4 + 2) * 132 + j] = v.z;
            sWt[(kq * 4 + 3) * 132 + j] = v.w;
        }
        __syncthreads();
        #pragma unroll
        for (int kk = 0; kk < 16; kk++) {
            longlong2 ha = *(const longlong2*)(sA + kk * 68 + bg * 8);
            longlong2 hb = *(const longlong2*)(sA + kk * 68 + bg * 8 + 4);
            float4 w0 = *(const float4*)(sWt + kk * 132 + jg * 8);
            float4 w1 = *(const float4*)(sWt + kk * 132 + jg * 8 + 4);
            u64 hq[4] = { (u64)ha.x, (u64)ha.y, (u64)hb.x, (u64)hb.y };
            u64 p[8]  = { pack2(w0.x, w0.x), pack2(w0.y, w0.y),
                          pack2(w0.z, w0.z), pack2(w0.w, w0.w),
                          pack2(w1.x, w1.x), pack2(w1.y, w1.y),
                          pack2(w1.z, w1.z), pack2(w1.w, w1.w) };
            #pragma unroll
            for (int jl = 0; jl < 8; jl++)
                #pragma unroll
                for (int bp = 0; bp < 4; bp++)
                    fma2(acc[jl * 4 + bp], hq[bp], p[jl]);
        }
    }
    #pragma unroll
    for (int jl = 0; jl < 8; jl++) {
        float* orow = g_xg + ((size_t)t * G4 + j0 + jg * 8 + jl) * BB + bg * 8;
        *(u64*)(orow + 0) = acc[jl * 4 + 0];
        *(u64*)(orow + 2) = acc[jl * 4 + 1];
        *(u64*)(orow + 4) = acc[jl * 4 + 2];
        *(u64*)(orow + 6) = acc[jl * 4 + 3];
    }
}

// ---- persistent LSTM layer via mma.sync (HMMA) ----
// CTA cb: gate cols j = g*HH + cb*8 + c (n=g*8+c, n in [0,32)).
// D[64x32] = h[64x1024] x W[32x1024]^T, 3-product bf16 split, fp32 accum.
// 8 warps: bh=wid&1 (batch half, 32 rows), ks=wid>>1 (k-split, 256 k each).
// Warp tile 32x32, k streamed in 8 chunks of 128 (each warp takes its 32-k slice per chunk).
__global__ __launch_bounds__(256) void lstm_layer_tc(const float* __restrict__ Whh, int layer)
{
    extern __shared__ char smem[];
    const int tid  = threadIdx.x;
    const int cb   = blockIdx.x;
    const int wid  = tid >> 5;
    const int lane = tid & 31;
    const int g8   = lane >> 2;
    const int tg   = lane & 3;
    const int bh   = wid & 1;
    const int ks   = wid >> 1;

    // ---- one-time: stage split W slice into smem ----
    {
        uint16_t* whi = (uint16_t*)(smem + SM_WHI);
        uint16_t* wlo = (uint16_t*)(smem + SM_WLO);
        for (int i = tid; i < 32 * HH; i += 256) {
            int n = i >> 10, k = i & 1023;
            int j = (n >> 3) * HH + cb * 8 + (n & 7);
            float w = Whh[(size_t)j * HH + k];
            __nv_bfloat16 h16 = __float2bfloat16(w);
            __nv_bfloat16 l16 = __float2bfloat16(w - __bfloat162float(h16));
            whi[n * WPIT + k] = *(uint16_t*)&h16;
            wlo[n * WPIT + k] = *(uint16_t*)&l16;
        }
    }
    __syncthreads();

    float cs[2][4];                     // cell state (warps 0-1 only), [rb][q]
    #pragma unroll
    for (int rb = 0; rb < 2; rb++)
        #pragma unroll
        for (int q = 0; q < 4; q++) cs[rb][q] = 0.0f;

    const int srow = tid >> 4;          // staging row 0..15 block -> actually idx>>4 below
    (void)srow;

    for (int t = 0; t < TT; t++) {
        float acc[2][4][4];             // [rowblock][ntile][frag]
        #pragma unroll
        for (int rb = 0; rb < 2; rb++)
            #pragma unroll
            for (int nt = 0; nt < 4; nt++)
                #pragma unroll
                for (int q = 0; q < 4; q++) acc[rb][nt][q] = 0.0f;

        if (t > 0) {
            const __nv_bfloat16* shi = g_hhi[(t - 1) & 1];
            const __nv_bfloat16* slo = g_hlo[(t - 1) & 1];

            // prefetch chunk 0: 4 uint4 per plane per thread
            uint4 pf[2][4];
            #pragma unroll
            for (int q = 0; q < 4; q++) {
                int idx = q * 256 + tid;         // 0..1023
                int row = idx >> 4, kq = idx & 15;
                size_t off = (size_t)row * HH + kq * 8;
                pf[0][q] = __ldcg((const uint4*)(shi + off));
                pf[1][q] = __ldcg((const uint4*)(slo + off));
            }

            for (int c = 0; c < 8; c++) {
                char* hbuf = smem + SM_H + (c & 1) * 2 * HPLANE;
                // store prefetched chunk
                #pragma unroll
                for (int q = 0; q < 4; q++) {
                    int idx = q * 256 + tid;
                    int row = idx >> 4, kq = idx & 15;
                    *(uint4*)(hbuf + row * (HPIT * 2) + kq * 16) = pf[0][q];
                    *(uint4*)(hbuf + HPLANE + row * (HPIT * 2) + kq * 16) = pf[1][q];
                }
                __syncthreads();   // store visible; also guarantees mma(c-1) done before next overwrite

                if (c < 7) {
                    #pragma unroll
                    for (int q = 0; q < 4; q++) {
                        int idx = q * 256 + tid;
                        int row = idx >> 4, kq = idx & 15;
                        size_t off = (size_t)row * HH + (c + 1) * 128 + kq * 8;
                        pf[0][q] = __ldcg((const uint4*)(shi + off));
                        pf[1][q] = __ldcg((const uint4*)(slo + off));
                    }
                }

                // mma on this chunk: warp handles k-local [ks*32, ks*32+32)
                const uint16_t* hhi = (const uint16_t*)hbuf;
                const uint16_t* hlo = (const uint16_t*)(hbuf + HPLANE);
                const uint16_t* whi = (const uint16_t*)(smem + SM_WHI);
                const uint16_t* wlo = (const uint16_t*)(smem + SM_WLO);

                #pragma unroll
                for (int kst = 0; kst < 2; kst++) {
                    const int kk = ks * 32 + kst * 16;       // k-local in chunk
                    const int kg = c * 128 + kk;             // global k (for W)
                    uint32_t Ahi[2][4], Alo[2][4], Bhi[4][2], Blo[4][2];
                    #pragma unroll
                    for (int rb = 0; rb < 2; rb++) {
                        const uint16_t* p = hhi + (bh * 32 + rb * 16 + g8) * HPIT + kk + tg * 2;
                        Ahi[rb][0] = *(const uint32_t*)p;
                        Ahi[rb][1] = *(const uint32_t*)(p + 8 * HPIT);
                        Ahi[rb][2] = *(const uint32_t*)(p + 8);
                        Ahi[rb][3] = *(const uint32_t*)(p + 8 * HPIT + 8);
                        const uint16_t* pl = hlo + (bh * 32 + rb * 16 + g8) * HPIT + kk + tg * 2;
                        Alo[rb][0] = *(const uint32_t*)pl;
                        Alo[rb][1] = *(const uint32_t*)(pl + 8 * HPIT);
                        Alo[rb][2] = *(const uint32_t*)(pl + 8);
                        Alo[rb][3] = *(const uint32_t*)(pl + 8 * HPIT + 8);
                    }
                    #pragma unroll
                    for (int nt = 0; nt < 4; nt++) {
                        const uint16_t* p = whi + (nt * 8 + g8) * WPIT + kg + tg * 2;
                        Bhi[nt][0] = *(const uint32_t*)p;
                        Bhi[nt][1] = *(const uint32_t*)(p + 8);
                        const uint16_t* pl = wlo + (nt * 8 + g8) * WPIT + kg + tg * 2;
                        Blo[nt][0] = *(const uint32_t*)pl;
                        Blo[nt][1] = *(const uint32_t*)(pl + 8);
                    }
                    #pragma unroll
                    for (int rb = 0; rb < 2; rb++)
                        #pragma unroll
                        for (int nt = 0; nt < 4; nt++) {
                            mma16816(acc[rb][nt], Ahi[rb], Bhi[nt]);
                            mma16816(acc[rb][nt], Ahi[rb], Blo[nt]);
                            mma16816(acc[rb][nt], Alo[rb], Bhi[nt]);
                        }
                }
            }

            // ---- 4-way k-split reduction via smem ----
            float* sred = (float*)(smem + SM_RED);
            __syncthreads();
            if (ks == 1 || ks == 3) {
                int s = bh * 2 + (ks >> 1);
                #pragma unroll
                for (int rb = 0; rb < 2; rb++)
                    #pragma unroll
                    for (int nt = 0; nt < 4; nt++)
                        #pragma unroll
                        for (int q = 0; q < 4; q++)
                            sred[(s * 32 + rb * 16 + nt * 4 + q) * 33 + lane] = acc[rb][nt][q];
            }
            __syncthreads();
            if (ks == 0 || ks == 2) {
                int s = bh * 2 + (ks >> 1);
                #pragma unroll
                for (int rb = 0; rb < 2; rb++)
                    #pragma unroll
                    for (int nt = 0; nt < 4; nt++)
                        #pragma unroll
                        for (int q = 0; q < 4; q++)
                            acc[rb][nt][q] += sred[(s * 32 + rb * 16 + nt * 4 + q) * 33 + lane];
            }
            __syncthreads();
            if (ks == 2) {
                int s = bh * 2;
                #pragma unroll
                for (int rb = 0; rb < 2; rb++)
                    #pragma unroll
                    for (int nt = 0; nt < 4; nt++)
                        #pragma unroll
                        for (int q = 0; q < 4; q++)
                            sred[(s * 32 + rb * 16 + nt * 4 + q) * 33 + lane] = acc[rb][nt][q];
            }
            __syncthreads();
            if (ks == 0) {
                int s = bh * 2;
                #pragma unroll
                for (int rb = 0; rb < 2; rb++)
                    #pragma unroll
                    for (int nt = 0; nt < 4; nt++)
                        #pragma unroll
                        for (int q = 0; q < 4; q++)
                            acc[rb][nt][q] += sred[(s * 32 + rb * 16 + nt * 4 + q) * 33 + lane];
            }
        }

        // ---- epilogue: warps 0-1 (ks==0) own full D; all gates lane-local ----
        if (wid < 2) {
            const float* xg = g_xg + (size_t)t * G4 * BB;
            #pragma unroll
            for (int rb = 0; rb < 2; rb++) {
                #pragma unroll
                for (int q = 0; q < 4; q++) {
                    int b  = bh * 32 + rb * 16 + g8 + ((q >> 1) ? 8 : 0);
                    int cc = tg * 2 + (q & 1);
                    int jb = cb * 8 + cc;
                    float gi = acc[rb][0][q] + xg[(size_t)(0 * HH + jb) * BB + b];
                    float gf = acc[rb][1][q] + xg[(size_t)(1 * HH + jb) * BB + b];
                    float gg = acc[rb][2][q] + xg[(size_t)(2 * HH + jb) * BB + b];
                    float go = acc[rb][3][q] + xg[(size_t)(3 * HH + jb) * BB + b];
                    float cnew = sigm(gf) * cs[rb][q] + sigm(gi) * tanhf(gg);
                    float hnew = sigm(go) * tanhf(cnew);
                    cs[rb][q] = cnew;
                    if (layer == 0)
                        g_h1[(size_t)t * HH * BB + (size_t)jb * BB + b] = hnew;
                    else if (t == TT - 1)
                        g_h2[(size_t)jb * BB + b] = hnew;
                    __nv_bfloat16 h16 = __float2bfloat16(hnew);
                    __nv_bfloat16 l16 = __float2bfloat16(hnew - __bfloat162float(h16));
                    g_hhi[t & 1][(size_t)b * HH + jb] = h16;
                    g_hlo[t & 1][(size_t)b * HH + jb] = l16;
                }
            }
        }

        // ---- global barrier ----
        if (t < TT - 1) {
            __threadfence();
            __syncthreads();
            if (tid == 0) {
                atomicAdd(&g_bar[t], 1);
                while (*(volatile int*)(g_bar + t) < NCTA) { }
            }
            __syncthreads();
        }
    }
}

// ---- head: out[b][r] = sum_k h2[k][b] * Wh[r][k] + bh[r] ----
__global__ __launch_bounds__(128) void head_kernel(
    const float* __restrict__ Wh, const float* __restrict__ bh, float* __restrict__ out)
{
    __shared__ float red[4];
    const int r = blockIdx.x, b = blockIdx.y;
    const int tid = threadIdx.x;

    float s = 0.0f;
    for (int k = tid; k < HH; k += 128) s += g_h2[(size_t)k * BB + b] * Wh[(size_t)r * HH + k];
    #pragma unroll
    for (int o = 16; o > 0; o >>= 1) s += __shfl_down_sync(0xFFFFFFFFu, s, o);
    if ((tid & 31) == 0) red[tid >> 5] = s;
    __syncthreads();
    if (tid == 0) out[b * HOR + r] = red[0] + red[1] + red[2] + red[3] + bh[r];
}

extern "C" void kernel_launch(void* const* d_in, const int* in_sizes, int n_in,
                              void* d_out, int out_size) {
    const float* x     = (const float*)d_in[0];
    const float* Wih0  = (const float*)d_in[1];
    const float* Whh0  = (const float*)d_in[2];
    const float* bih0  = (const float*)d_in[3];
    const float* bhh0  = (const float*)d_in[4];
    const float* Wih1  = (const float*)d_in[5];
    const float* Whh1  = (const float*)d_in[6];
    const float* bih1  = (const float*)d_in[7];
    const float* bhh1  = (const float*)d_in[8];
    const float* Whead = (const float*)d_in[9];
    const float* bhead = (const float*)d_in[10];
    float* out = (float*)d_out;

    static int configured = 0;
    if (!configured) {
        cudaFuncSetAttribute(lstm_layer_tc,
                             cudaFuncAttributeMaxDynamicSharedMemorySize, SMEM_TC);
        configured = 1;
    }

    // layer 0
    zero_state<<<2, 256>>>();
    gemm_xg<<<dim3(G4 / 128, TT), 128>>>(x, Wih0, bih0, bhh0, 0);
    lstm_layer_tc<<<NCTA, 256, SMEM_TC>>>(Whh0, 0);

    // layer 1
    zero_state<<<2, 256>>>();
    gemm_xg<<<dim3(G4 / 128, TT), 128>>>(x, Wih1, bih1, bhh1, 1);
    lstm_layer_tc<<<NCTA, 256, SMEM_TC>>>(Whh1, 1);

    // head
    head_kernel<<<dim3(HOR, BB), 128>>>(Whead, bhead, out);
}

// round 13
// speedup vs baseline: 4.5098x; 1.1158x over previous
#include <cuda_runtime.h>
#include <cuda_bf16.h>
#include <cstdint>

#define BB   64
#define TT   512
#define II   256
#define HH   1024
#define G4   4096
#define HOR  24
#define NCTA 128

typedef unsigned long long u64;
typedef uint32_t u32;
typedef uint16_t u16;

// ---- scratch (device globals; allocation-free) ----
__device__ float g_xg[(size_t)TT * G4 * BB];        // [T][4H][B]
__device__ float g_h1[(size_t)TT * HH * BB];        // [T][H][B] fp32 (layer0 history for gemm)
__device__ float g_h2[HH * BB];                     // layer1 final h [jb][b]
__device__ __nv_bfloat16 g_hhi[2][(size_t)BB * HH]; // ping-pong split h, [b][k]
__device__ __nv_bfloat16 g_hlo[2][(size_t)BB * HH];
__device__ int g_bar[TT];

// ---- scalar helpers ----
__device__ __forceinline__ u64 pack2(float lo, float hi) {
    u64 r; asm("mov.b64 %0, {%1, %2};" : "=l"(r) : "f"(lo), "f"(hi)); return r;
}
__device__ __forceinline__ void fma2(u64& d, u64 a, u64 b) {
    asm("fma.rn.f32x2 %0, %1, %2, %0;" : "+l"(d) : "l"(a), "l"(b));
}
__device__ __forceinline__ float sigm(float x) { return 1.0f / (1.0f + __expf(-x)); }

// m16n8k16 bf16 mma, accumulate in place
__device__ __forceinline__ void mma16816(float* d, const u32* a, const u32* b) {
    asm volatile(
        "mma.sync.aligned.m16n8k16.row.col.f32.bf16.bf16.f32 "
        "{%0,%1,%2,%3}, {%4,%5,%6,%7}, {%8,%9}, {%0,%1,%2,%3};\n"
        : "+f"(d[0]), "+f"(d[1]), "+f"(d[2]), "+f"(d[3])
        : "r"(a[0]), "r"(a[1]), "r"(a[2]), "r"(a[3]), "r"(b[0]), "r"(b[1]));
}

// ---- zero barrier counters ----
__global__ void zero_state() {
    int i = blockIdx.x * blockDim.x + threadIdx.x;
    if (i < TT) g_bar[i] = 0;
}

// ---- input projection GEMM (fp32 FFMA2, proven R7/R9) ----
// mode 0: A = x[b][t][k], K=II.  mode 1: A = g_h1[t][k][b], K=HH.
__global__ __launch_bounds__(128) void gemm_xg(
    const float* __restrict__ X, const float* __restrict__ W,
    const float* __restrict__ bih, const float* __restrict__ bhh, int mode)
{
    __shared__ __align__(16) float sA[16 * 68];
    __shared__ __align__(16) float sWt[16 * 132];
    __shared__ float sBias[128];

    const int tid = threadIdx.x;
    const int t   = blockIdx.y;
    const int j0  = blockIdx.x * 128;
    const int K   = mode ? HH : II;
    const int jg  = tid & 15;
    const int bg  = tid >> 4;

    sBias[tid] = bih[j0 + tid] + bhh[j0 + tid];
    __syncthreads();

    u64 acc[32];
    #pragma unroll
    for (int jl = 0; jl < 8; jl++) {
        float bj = sBias[jg * 8 + jl];
        u64 p = pack2(bj, bj);
        acc[jl * 4 + 0] = p; acc[jl * 4 + 1] = p;
        acc[jl * 4 + 2] = p; acc[jl * 4 + 3] = p;
    }

    for (int k0 = 0; k0 < K; k0 += 16) {
        __syncthreads();
        if (mode == 0) {
            #pragma unroll
            for (int q = 0; q < 2; q++) {
                int f = q * 128 + tid;
                int b = f >> 2, kq = f & 3;
                float4 v = *(const float4*)(X + ((size_t)b * TT + t) * II + k0 + kq * 4);
                sA[(kq * 4 + 0) * 68 + b] = v.x;
                sA[(kq * 4 + 1) * 68 + b] = v.y;
                sA[(kq * 4 + 2) * 68 + b] = v.z;
                sA[(kq * 4 + 3) * 68 + b] = v.w;
            }
        } else {
            #pragma unroll
            for (int q = 0; q < 2; q++) {
                int f = q * 128 + tid;
                int kk = f >> 4, b4 = f & 15;
                float4 v = *(const float4*)(g_h1 + ((size_t)t * HH + k0 + kk) * BB + b4 * 4);
                *(float4*)(sA + kk * 68 + b4 * 4) = v;
            }
        }
        #pragma unroll
        for (int q = 0; q < 4; q++) {
            int f = q * 128 + tid;
            int j = f >> 2, kq = f & 3;
            float4 v = *(const float4*)(W + (size_t)(j0 + j) * K + k0 + kq * 4);
            sWt[(kq * 4 + 0) * 132 + j] = v.x;
            sWt[(kq * 4 + 1) * 132 + j] = v.y;
            sWt[(kq * 4 + 2) * 132 + j] = v.z;
            sWt[(kq * 4 + 3) * 132 + j] = v.w;
        }
        __syncthreads();
        #pragma unroll
        for (int kk = 0; kk < 16; kk++) {
            longlong2 ha = *(const longlong2*)(sA + kk * 68 + bg * 8);
            longlong2 hb = *(const longlong2*)(sA + kk * 68 + bg * 8 + 4);
            float4 w0 = *(const float4*)(sWt + kk * 132 + jg * 8);
            float4 w1 = *(const float4*)(sWt + kk * 132 + jg * 8 + 4);
            u64 hq[4] = { (u64)ha.x, (u64)ha.y, (u64)hb.x, (u64)hb.y };
            u64 p[8]  = { pack2(w0.x, w0.x), pack2(w0.y, w0.y),
                          pack2(w0.z, w0.z), pack2(w0.w, w0.w),
                          pack2(w1.x, w1.x), pack2(w1.y, w1.y),
                          pack2(w1.z, w1.z), pack2(w1.w, w1.w) };
            #pragma unroll
            for (int jl = 0; jl < 8; jl++)
                #pragma unroll
                for (int bp = 0; bp < 4; bp++)
                    fma2(acc[jl * 4 + bp], hq[bp], p[jl]);
        }
    }
    #pragma unroll
    for (int jl = 0; jl < 8; jl++) {
        float* orow = g_xg + ((size_t)t * G4 + j0 + jg * 8 + jl) * BB + bg * 8;
        *(u64*)(orow + 0) = acc[jl * 4 + 0];
        *(u64*)(orow + 2) = acc[jl * 4 + 1];
        *(u64*)(orow + 4) = acc[jl * 4 + 2];
        *(u64*)(orow + 6) = acc[jl * 4 + 3];
    }
}

// ---- persistent LSTM layer via mma.sync (R9 base + sXG prefetch + 1-round reduction) ----
#define WPIT   1032
#define HPIT   136
#define SM_WHI 0
#define SM_WLO (32 * WPIT * 2)                 // 66048
#define SM_H   (SM_WLO + 32 * WPIT * 2)        // 132096
#define HPLANE (64 * HPIT * 2)                 // 17408
#define SM_XG  (SM_H + 4 * HPLANE)             // 201728; 32x68 f32 = 8704
#define SMEM_TC (SM_XG + 32 * 68 * 4)          // 210432

__global__ __launch_bounds__(256) void lstm_layer_tc(const float* __restrict__ Whh, int layer)
{
    extern __shared__ char smem[];
    const int tid  = threadIdx.x;
    const int cb   = blockIdx.x;
    const int wid  = tid >> 5;
    const int lane = tid & 31;
    const int g8   = lane >> 2;
    const int tg   = lane & 3;
    const int bh   = wid & 1;
    const int ks   = wid >> 1;

    // one-time: stage split W slice
    {
        u16* whi = (u16*)(smem + SM_WHI);
        u16* wlo = (u16*)(smem + SM_WLO);
        for (int i = tid; i < 32 * HH; i += 256) {
            int n = i >> 10, k = i & 1023;
            int j = (n >> 3) * HH + cb * 8 + (n & 7);
            float w = Whh[(size_t)j * HH + k];
            __nv_bfloat16 h16 = __float2bfloat16(w);
            __nv_bfloat16 l16 = __float2bfloat16(w - __bfloat162float(h16));
            whi[n * WPIT + k] = *(u16*)&h16;
            wlo[n * WPIT + k] = *(u16*)&l16;
        }
    }
    __syncthreads();

    float cs[2][4];
    #pragma unroll
    for (int rb = 0; rb < 2; rb++)
        #pragma unroll
        for (int q = 0; q < 4; q++) cs[rb][q] = 0.0f;

    float* sXG = (float*)(smem + SM_XG);
    // sXG load indices: row r covers gate (r>>3), cell (r&7); 16 floats/seg group
    const int xr0 = tid >> 4,        xs0 = tid & 15;       // rows 0..15
    const int xr1 = (256 + tid) >> 4, xs1 = tid & 15;      // rows 16..31

    for (int t = 0; t < TT; t++) {
        // xg[t] is pre-computed before this kernel: load early, no barrier dependence
        const float* xg = g_xg + (size_t)t * G4 * BB;
        float4 xga = __ldcg((const float4*)(xg
                        + (size_t)((xr0 >> 3) * HH + cb * 8 + (xr0 & 7)) * BB + xs0 * 4));
        float4 xgb = __ldcg((const float4*)(xg
                        + (size_t)((xr1 >> 3) * HH + cb * 8 + (xr1 & 7)) * BB + xs1 * 4));

        float acc[2][4][4];
        #pragma unroll
        for (int rb = 0; rb < 2; rb++)
            #pragma unroll
            for (int nt = 0; nt < 4; nt++)
                #pragma unroll
                for (int q = 0; q < 4; q++) acc[rb][nt][q] = 0.0f;

        if (t > 0) {
            const __nv_bfloat16* shi = g_hhi[(t - 1) & 1];
            const __nv_bfloat16* slo = g_hlo[(t - 1) & 1];

            uint4 pf[2][4];
            #pragma unroll
            for (int q = 0; q < 4; q++) {
                int idx = q * 256 + tid;
                int row = idx >> 4, kq = idx & 15;
                size_t off = (size_t)row * HH + kq * 8;
                pf[0][q] = __ldcg((const uint4*)(shi + off));
                pf[1][q] = __ldcg((const uint4*)(slo + off));
            }

            for (int c = 0; c < 8; c++) {
                char* hbuf = smem + SM_H + (c & 1) * 2 * HPLANE;
                #pragma unroll
                for (int q = 0; q < 4; q++) {
                    int idx = q * 256 + tid;
                    int row = idx >> 4, kq = idx & 15;
                    *(uint4*)(hbuf + row * (HPIT * 2) + kq * 16) = pf[0][q];
                    *(uint4*)(hbuf + HPLANE + row * (HPIT * 2) + kq * 16) = pf[1][q];
                }
                __syncthreads();

                if (c < 7) {
                    #pragma unroll
                    for (int q = 0; q < 4; q++) {
                        int idx = q * 256 + tid;
                        int row = idx >> 4, kq = idx & 15;
                        size_t off = (size_t)row * HH + (c + 1) * 128 + kq * 8;
                        pf[0][q] = __ldcg((const uint4*)(shi + off));
                        pf[1][q] = __ldcg((const uint4*)(slo + off));
                    }
                }

                const u16* hhi = (const u16*)hbuf;
                const u16* hlo = (const u16*)(hbuf + HPLANE);
                const u16* whi = (const u16*)(smem + SM_WHI);
                const u16* wlo = (const u16*)(smem + SM_WLO);

                #pragma unroll
                for (int kst = 0; kst < 2; kst++) {
                    const int kk = ks * 32 + kst * 16;
                    const int kg = c * 128 + kk;
                    u32 Ahi[2][4], Alo[2][4], Bhi[4][2], Blo[4][2];
                    #pragma unroll
                    for (int rb = 0; rb < 2; rb++) {
                        const u16* p = hhi + (bh * 32 + rb * 16 + g8) * HPIT + kk + tg * 2;
                        Ahi[rb][0] = *(const u32*)p;
                        Ahi[rb][1] = *(const u32*)(p + 8 * HPIT);
                        Ahi[rb][2] = *(const u32*)(p + 8);
                        Ahi[rb][3] = *(const u32*)(p + 8 * HPIT + 8);
                        const u16* pl = hlo + (bh * 32 + rb * 16 + g8) * HPIT + kk + tg * 2;
                        Alo[rb][0] = *(const u32*)pl;
                        Alo[rb][1] = *(const u32*)(pl + 8 * HPIT);
                        Alo[rb][2] = *(const u32*)(pl + 8);
                        Alo[rb][3] = *(const u32*)(pl + 8 * HPIT + 8);
                    }
                    #pragma unroll
                    for (int nt = 0; nt < 4; nt++) {
                        const u16* p = whi + (nt * 8 + g8) * WPIT + kg + tg * 2;
                        Bhi[nt][0] = *(const u32*)p;
                        Bhi[nt][1] = *(const u32*)(p + 8);
                        const u16* pl = wlo + (nt * 8 + g8) * WPIT + kg + tg * 2;
                        Blo[nt][0] = *(const u32*)pl;
                        Blo[nt][1] = *(const u32*)(pl + 8);
                    }
                    #pragma unroll
                    for (int rb = 0; rb < 2; rb++)
                        #pragma unroll
                        for (int nt = 0; nt < 4; nt++) {
                            mma16816(acc[rb][nt], Ahi[rb], Bhi[nt]);
                            mma16816(acc[rb][nt], Ahi[rb], Blo[nt]);
                            mma16816(acc[rb][nt], Alo[rb], Bhi[nt]);
                        }
                }
            }
        }

        // publish xg block to smem (dedicated region; no hazard with mma buffers)
        *(float4*)(sXG + xr0 * 68 + xs0 * 4) = xga;
        *(float4*)(sXG + xr1 * 68 + xs1 * 4) = xgb;
        __syncthreads();

        if (t > 0) {
            // single-round 4-way k-split reduction, overlaid on freed SM_H region.
            // writers ks in {1,2,3}: slot s=(ks-1)*2+bh (6 slots, disjoint; 25344 B,
            // entirely inside chunk-buffer-0 region [0,34816) — chunk 7 used buffer 1).
            float* red = (float*)(smem + SM_H);
            if (ks > 0) {
                int s = (ks - 1) * 2 + bh;
                #pragma unroll
                for (int rb = 0; rb < 2; rb++)
                    #pragma unroll
                    for (int nt = 0; nt < 4; nt++)
                        #pragma unroll
                        for (int q = 0; q < 4; q++)
                            red[(size_t)s * (32 * 33) + (rb * 16 + nt * 4 + q) * 33 + lane]
                                = acc[rb][nt][q];
            }
            __syncthreads();
            if (ks == 0) {
                #pragma unroll
                for (int s = 0; s < 3; s++)
                    #pragma unroll
                    for (int rb = 0; rb < 2; rb++)
                        #pragma unroll
                        for (int nt = 0; nt < 4; nt++)
                            #pragma unroll
                            for (int q = 0; q < 4; q++)
                                acc[rb][nt][q] +=
                                    red[(size_t)(s * 2 + bh) * (32 * 33)
                                        + (rb * 16 + nt * 4 + q) * 33 + lane];
            }
        }

        // ---- epilogue: warps 0-1 (ks==0); gates lane-local; xg from smem ----
        if (wid < 2) {
            #pragma unroll
            for (int rb = 0; rb < 2; rb++) {
                #pragma unroll
                for (int q = 0; q < 4; q++) {
                    int b  = bh * 32 + rb * 16 + g8 + ((q >> 1) ? 8 : 0);
                    int cc = tg * 2 + (q & 1);
                    int jb = cb * 8 + cc;
                    float gi = acc[rb][0][q] + sXG[(0  + cc) * 68 + b];
                    float gf = acc[rb][1][q] + sXG[(8  + cc) * 68 + b];
                    float gg = acc[rb][2][q] + sXG[(16 + cc) * 68 + b];
                    float go = acc[rb][3][q] + sXG[(24 + cc) * 68 + b];
                    float cnew = sigm(gf) * cs[rb][q] + sigm(gi) * tanhf(gg);
                    float hnew = sigm(go) * tanhf(cnew);
                    cs[rb][q] = cnew;
                    __nv_bfloat16 h16 = __float2bfloat16(hnew);
                    __nv_bfloat16 l16 = __float2bfloat16(hnew - __bfloat162float(h16));
                    if (layer == 0)
                        g_h1[(size_t)t * HH * BB + (size_t)jb * BB + b] = hnew;
                    else if (t == TT - 1)
                        g_h2[(size_t)jb * BB + b] = hnew;
                    g_hhi[t & 1][(size_t)b * HH + jb] = h16;
                    g_hlo[t & 1][(size_t)b * HH + jb] = l16;
                }
            }
        }

        // ---- global barrier (R9 exact) ----
        if (t < TT - 1) {
            __threadfence();
            __syncthreads();
            if (tid == 0) {
                atomicAdd(&g_bar[t], 1);
                while (*(volatile int*)(g_bar + t) < NCTA) { }
            }
            __syncthreads();
        }
    }
}

// ---- head ----
__global__ __launch_bounds__(128) void head_kernel(
    const float* __restrict__ Wh, const float* __restrict__ bh, float* __restrict__ out)
{
    __shared__ float red[4];
    const int r = blockIdx.x, b = blockIdx.y;
    const int tid = threadIdx.x;

    float s = 0.0f;
    for (int k = tid; k < HH; k += 128) s += g_h2[(size_t)k * BB + b] * Wh[(size_t)r * HH + k];
    #pragma unroll
    for (int o = 16; o > 0; o >>= 1) s += __shfl_down_sync(0xFFFFFFFFu, s, o);
    if ((tid & 31) == 0) red[tid >> 5] = s;
    __syncthreads();
    if (tid == 0) out[b * HOR + r] = red[0] + red[1] + red[2] + red[3] + bh[r];
}

extern "C" void kernel_launch(void* const* d_in, const int* in_sizes, int n_in,
                              void* d_out, int out_size) {
    const float* x     = (const float*)d_in[0];
    const float* Wih0  = (const float*)d_in[1];
    const float* Whh0  = (const float*)d_in[2];
    const float* bih0  = (const float*)d_in[3];
    const float* bhh0  = (const float*)d_in[4];
    const float* Wih1  = (const float*)d_in[5];
    const float* Whh1  = (const float*)d_in[6];
    const float* bih1  = (const float*)d_in[7];
    const float* bhh1  = (const float*)d_in[8];
    const float* Whead = (const float*)d_in[9];
    const float* bhead = (const float*)d_in[10];
    float* out = (float*)d_out;

    static int configured = 0;
    if (!configured) {
        cudaFuncSetAttribute(lstm_layer_tc,
                             cudaFuncAttributeMaxDynamicSharedMemorySize, SMEM_TC);
        configured = 1;
    }

    // layer 0
    zero_state<<<2, 256>>>();
    gemm_xg<<<dim3(G4 / 128, TT), 128>>>(x, Wih0, bih0, bhh0, 0);
    lstm_layer_tc<<<NCTA, 256, SMEM_TC>>>(Whh0, 0);

    // layer 1
    zero_state<<<2, 256>>>();
    gemm_xg<<<dim3(G4 / 128, TT), 128>>>(x, Wih1, bih1, bhh1, 1);
    lstm_layer_tc<<<NCTA, 256, SMEM_TC>>>(Whh1, 1);

    // head
    head_kernel<<<dim3(HOR, BB), 128>>>(Whead, bhead, out);
}

// round 14
// speedup vs baseline: 4.8310x; 1.0712x over previous
#include <cuda_runtime.h>
#include <cuda_bf16.h>
#include <cstdint>

#define BB   64
#define TT   512
#define II   256
#define HH   1024
#define G4   4096
#define HOR  24
#define NCTA 128

typedef unsigned long long u64;
typedef uint32_t u32;
typedef uint16_t u16;

// ---- scratch (device globals; allocation-free) ----
__device__ float g_xg[(size_t)TT * G4 * BB];           // [T][4H][B]
__device__ float g_h2[HH * BB];                        // layer1 final h [jb][b]
__device__ __nv_bfloat16 g_hhi[2][(size_t)BB * HH];    // ping-pong split h, [b][k]
__device__ __nv_bfloat16 g_hlo[2][(size_t)BB * HH];
__device__ __nv_bfloat16 g_h1hi[(size_t)TT * BB * HH]; // layer0 h history split hi, [t][b][k]
__device__ __nv_bfloat16 g_h1lo[(size_t)TT * BB * HH]; // layer0 h history split lo
__device__ int g_bar[TT];

// ---- scalar helpers ----
__device__ __forceinline__ u64 pack2(float lo, float hi) {
    u64 r; asm("mov.b64 %0, {%1, %2};" : "=l"(r) : "f"(lo), "f"(hi)); return r;
}
__device__ __forceinline__ void fma2(u64& d, u64 a, u64 b) {
    asm("fma.rn.f32x2 %0, %1, %2, %0;" : "+l"(d) : "l"(a), "l"(b));
}
__device__ __forceinline__ float sigm(float x) { return 1.0f / (1.0f + __expf(-x)); }

// m16n8k16 bf16 mma, accumulate in place
__device__ __forceinline__ void mma16816(float* d, const u32* a, const u32* b) {
    asm volatile(
        "mma.sync.aligned.m16n8k16.row.col.f32.bf16.bf16.f32 "
        "{%0,%1,%2,%3}, {%4,%5,%6,%7}, {%8,%9}, {%0,%1,%2,%3};\n"
        : "+f"(d[0]), "+f"(d[1]), "+f"(d[2]), "+f"(d[3])
        : "r"(a[0]), "r"(a[1]), "r"(a[2]), "r"(a[3]), "r"(b[0]), "r"(b[1]));
}

// ---- zero barrier counters ----
__global__ void zero_state() {
    int i = blockIdx.x * blockDim.x + threadIdx.x;
    if (i < TT) g_bar[i] = 0;
}

// ---- layer-0 input projection GEMM (fp32 FFMA2, proven; K=II) ----
__global__ __launch_bounds__(128) void gemm0(
    const float* __restrict__ X, const float* __restrict__ W,
    const float* __restrict__ bih, const float* __restrict__ bhh)
{
    __shared__ __align__(16) float sA[16 * 68];
    __shared__ __align__(16) float sWt[16 * 132];
    __shared__ float sBias[128];

    const int tid = threadIdx.x;
    const int t   = blockIdx.y;
    const int j0  = blockIdx.x * 128;
    const int jg  = tid & 15;
    const int bg  = tid >> 4;

    sBias[tid] = bih[j0 + tid] + bhh[j0 + tid];
    __syncthreads();

    u64 acc[32];
    #pragma unroll
    for (int jl = 0; jl < 8; jl++) {
        float bj = sBias[jg * 8 + jl];
        u64 p = pack2(bj, bj);
        acc[jl * 4 + 0] = p; acc[jl * 4 + 1] = p;
        acc[jl * 4 + 2] = p; acc[jl * 4 + 3] = p;
    }

    for (int k0 = 0; k0 < II; k0 += 16) {
        __syncthreads();
        #pragma unroll
        for (int q = 0; q < 2; q++) {
            int f = q * 128 + tid;
            int b = f >> 2, kq = f & 3;
            float4 v = *(const float4*)(X + ((size_t)b * TT + t) * II + k0 + kq * 4);
            sA[(kq * 4 + 0) * 68 + b] = v.x;
            sA[(kq * 4 + 1) * 68 + b] = v.y;
            sA[(kq * 4 + 2) * 68 + b] = v.z;
            sA[(kq * 4 + 3) * 68 + b] = v.w;
        }
        #pragma unroll
        for (int q = 0; q < 4; q++) {
            int f = q * 128 + tid;
            int j = f >> 2, kq = f & 3;
            float4 v = *(const float4*)(W + (size_t)(j0 + j) * II + k0 + kq * 4);
            sWt[(kq * 4 + 0) * 132 + j] = v.x;
            sWt[(kq * 4 + 1) * 132 + j] = v.y;
            sWt[(kq * 4 + 2) * 132 + j] = v.z;
            sWt[(kq * 4 + 3) * 132 + j] = v.w;
        }
        __syncthreads();
        #pragma unroll
        for (int kk = 0; kk < 16; kk++) {
            longlong2 ha = *(const longlong2*)(sA + kk * 68 + bg * 8);
            longlong2 hb = *(const longlong2*)(sA + kk * 68 + bg * 8 + 4);
            float4 w0 = *(const float4*)(sWt + kk * 132 + jg * 8);
            float4 w1 = *(const float4*)(sWt + kk * 132 + jg * 8 + 4);
            u64 hq[4] = { (u64)ha.x, (u64)ha.y, (u64)hb.x, (u64)hb.y };
            u64 p[8]  = { pack2(w0.x, w0.x), pack2(w0.y, w0.y),
                          pack2(w0.z, w0.z), pack2(w0.w, w0.w),
                          pack2(w1.x, w1.x), pack2(w1.y, w1.y),
                          pack2(w1.z, w1.z), pack2(w1.w, w1.w) };
            #pragma unroll
            for (int jl = 0; jl < 8; jl++)
                #pragma unroll
                for (int bp = 0; bp < 4; bp++)
                    fma2(acc[jl * 4 + bp], hq[bp], p[jl]);
        }
    }
    #pragma unroll
    for (int jl = 0; jl < 8; jl++) {
        float* orow = g_xg + ((size_t)t * G4 + j0 + jg * 8 + jl) * BB + bg * 8;
        *(u64*)(orow + 0) = acc[jl * 4 + 0];
        *(u64*)(orow + 2) = acc[jl * 4 + 1];
        *(u64*)(orow + 4) = acc[jl * 4 + 2];
        *(u64*)(orow + 6) = acc[jl * 4 + 3];
    }
}

// ---- smem layout shared by recurrence + xg1 kernels ----
#define WPIT   1032
#define HPIT   136
#define SM_WHI 0
#define SM_WLO (32 * WPIT * 2)                 // 66048
#define SM_H   (SM_WLO + 32 * WPIT * 2)        // 132096
#define HPLANE (64 * HPIT * 2)                 // 17408
#define SM_XG  (SM_H + 4 * HPLANE)             // 201728; 32x68 f32 = 8704
#define SMEM_TC (SM_XG + 32 * 68 * 4)          // 210432

// ---- persistent LSTM layer via mma.sync (R13 passing version) ----
__global__ __launch_bounds__(256) void lstm_layer_tc(const float* __restrict__ Whh, int layer)
{
    extern __shared__ char smem[];
    const int tid  = threadIdx.x;
    const int cb   = blockIdx.x;
    const int wid  = tid >> 5;
    const int lane = tid & 31;
    const int g8   = lane >> 2;
    const int tg   = lane & 3;
    const int bh   = wid & 1;
    const int ks   = wid >> 1;

    // one-time: stage split W slice
    {
        u16* whi = (u16*)(smem + SM_WHI);
        u16* wlo = (u16*)(smem + SM_WLO);
        for (int i = tid; i < 32 * HH; i += 256) {
            int n = i >> 10, k = i & 1023;
            int j = (n >> 3) * HH + cb * 8 + (n & 7);
            float w = Whh[(size_t)j * HH + k];
            __nv_bfloat16 h16 = __float2bfloat16(w);
            __nv_bfloat16 l16 = __float2bfloat16(w - __bfloat162float(h16));
            whi[n * WPIT + k] = *(u16*)&h16;
            wlo[n * WPIT + k] = *(u16*)&l16;
        }
    }
    __syncthreads();

    float cs[2][4];
    #pragma unroll
    for (int rb = 0; rb < 2; rb++)
        #pragma unroll
        for (int q = 0; q < 4; q++) cs[rb][q] = 0.0f;

    float* sXG = (float*)(smem + SM_XG);
    const int xr0 = tid >> 4,         xs0 = tid & 15;
    const int xr1 = (256 + tid) >> 4, xs1 = tid & 15;

    for (int t = 0; t < TT; t++) {
        const float* xg = g_xg + (size_t)t * G4 * BB;
        float4 xga = __ldcg((const float4*)(xg
                        + (size_t)((xr0 >> 3) * HH + cb * 8 + (xr0 & 7)) * BB + xs0 * 4));
        float4 xgb = __ldcg((const float4*)(xg
                        + (size_t)((xr1 >> 3) * HH + cb * 8 + (xr1 & 7)) * BB + xs1 * 4));

        float acc[2][4][4];
        #pragma unroll
        for (int rb = 0; rb < 2; rb++)
            #pragma unroll
            for (int nt = 0; nt < 4; nt++)
                #pragma unroll
                for (int q = 0; q < 4; q++) acc[rb][nt][q] = 0.0f;

        if (t > 0) {
            const __nv_bfloat16* shi = g_hhi[(t - 1) & 1];
            const __nv_bfloat16* slo = g_hlo[(t - 1) & 1];

            uint4 pf[2][4];
            #pragma unroll
            for (int q = 0; q < 4; q++) {
                int idx = q * 256 + tid;
                int row = idx >> 4, kq = idx & 15;
                size_t off = (size_t)row * HH + kq * 8;
                pf[0][q] = __ldcg((const uint4*)(shi + off));
                pf[1][q] = __ldcg((const uint4*)(slo + off));
            }

            for (int c = 0; c < 8; c++) {
                char* hbuf = smem + SM_H + (c & 1) * 2 * HPLANE;
                #pragma unroll
                for (int q = 0; q < 4; q++) {
                    int idx = q * 256 + tid;
                    int row = idx >> 4, kq = idx & 15;
                    *(uint4*)(hbuf + row * (HPIT * 2) + kq * 16) = pf[0][q];
                    *(uint4*)(hbuf + HPLANE + row * (HPIT * 2) + kq * 16) = pf[1][q];
                }
                __syncthreads();

                if (c < 7) {
                    #pragma unroll
                    for (int q = 0; q < 4; q++) {
                        int idx = q * 256 + tid;
                        int row = idx >> 4, kq = idx & 15;
                        size_t off = (size_t)row * HH + (c + 1) * 128 + kq * 8;
                        pf[0][q] = __ldcg((const uint4*)(shi + off));
                        pf[1][q] = __ldcg((const uint4*)(slo + off));
                    }
                }

                const u16* hhi = (const u16*)hbuf;
                const u16* hlo = (const u16*)(hbuf + HPLANE);
                const u16* whi = (const u16*)(smem + SM_WHI);
                const u16* wlo = (const u16*)(smem + SM_WLO);

                #pragma unroll
                for (int kst = 0; kst < 2; kst++) {
                    const int kk = ks * 32 + kst * 16;
                    const int kg = c * 128 + kk;
                    u32 Ahi[2][4], Alo[2][4], Bhi[4][2], Blo[4][2];
                    #pragma unroll
                    for (int rb = 0; rb < 2; rb++) {
                        const u16* p = hhi + (bh * 32 + rb * 16 + g8) * HPIT + kk + tg * 2;
                        Ahi[rb][0] = *(const u32*)p;
                        Ahi[rb][1] = *(const u32*)(p + 8 * HPIT);
                        Ahi[rb][2] = *(const u32*)(p + 8);
                        Ahi[rb][3] = *(const u32*)(p + 8 * HPIT + 8);
                        const u16* pl = hlo + (bh * 32 + rb * 16 + g8) * HPIT + kk + tg * 2;
                        Alo[rb][0] = *(const u32*)pl;
                        Alo[rb][1] = *(const u32*)(pl + 8 * HPIT);
                        Alo[rb][2] = *(const u32*)(pl + 8);
                        Alo[rb][3] = *(const u32*)(pl + 8 * HPIT + 8);
                    }
                    #pragma unroll
                    for (int nt = 0; nt < 4; nt++) {
                        const u16* p = whi + (nt * 8 + g8) * WPIT + kg + tg * 2;
                        Bhi[nt][0] = *(const u32*)p;
                        Bhi[nt][1] = *(const u32*)(p + 8);
                        const u16* pl = wlo + (nt * 8 + g8) * WPIT + kg + tg * 2;
                        Blo[nt][0] = *(const u32*)pl;
                        Blo[nt][1] = *(const u32*)(pl + 8);
                    }
                    #pragma unroll
                    for (int rb = 0; rb < 2; rb++)
                        #pragma unroll
                        for (int nt = 0; nt < 4; nt++) {
                            mma16816(acc[rb][nt], Ahi[rb], Bhi[nt]);
                            mma16816(acc[rb][nt], Ahi[rb], Blo[nt]);
                            mma16816(acc[rb][nt], Alo[rb], Bhi[nt]);
                        }
                }
            }
        }

        // publish xg block to smem
        *(float4*)(sXG + xr0 * 68 + xs0 * 4) = xga;
        *(float4*)(sXG + xr1 * 68 + xs1 * 4) = xgb;
        __syncthreads();

        if (t > 0) {
            // single-round 4-way k-split reduction (slots inside freed SM_H buffer 0)
            float* red = (float*)(smem + SM_H);
            if (ks > 0) {
                int s = (ks - 1) * 2 + bh;
                #pragma unroll
                for (int rb = 0; rb < 2; rb++)
                    #pragma unroll
                    for (int nt = 0; nt < 4; nt++)
                        #pragma unroll
                        for (int q = 0; q < 4; q++)
                            red[(size_t)s * (32 * 33) + (rb * 16 + nt * 4 + q) * 33 + lane]
                                = acc[rb][nt][q];
            }
            __syncthreads();
            if (ks == 0) {
                #pragma unroll
                for (int s = 0; s < 3; s++)
                    #pragma unroll
                    for (int rb = 0; rb < 2; rb++)
                        #pragma unroll
                        for (int nt = 0; nt < 4; nt++)
                            #pragma unroll
                            for (int q = 0; q < 4; q++)
                                acc[rb][nt][q] +=
                                    red[(size_t)(s * 2 + bh) * (32 * 33)
                                        + (rb * 16 + nt * 4 + q) * 33 + lane];
            }
        }

        // ---- epilogue: warps 0-1; gates lane-local; xg from smem ----
        if (wid < 2) {
            #pragma unroll
            for (int rb = 0; rb < 2; rb++) {
                #pragma unroll
                for (int q = 0; q < 4; q++) {
                    int b  = bh * 32 + rb * 16 + g8 + ((q >> 1) ? 8 : 0);
                    int cc = tg * 2 + (q & 1);
                    int jb = cb * 8 + cc;
                    float gi = acc[rb][0][q] + sXG[(0  + cc) * 68 + b];
                    float gf = acc[rb][1][q] + sXG[(8  + cc) * 68 + b];
                    float gg = acc[rb][2][q] + sXG[(16 + cc) * 68 + b];
                    float go = acc[rb][3][q] + sXG[(24 + cc) * 68 + b];
                    float cnew = sigm(gf) * cs[rb][q] + sigm(gi) * tanhf(gg);
                    float hnew = sigm(go) * tanhf(cnew);
                    cs[rb][q] = cnew;
                    __nv_bfloat16 h16 = __float2bfloat16(hnew);
                    __nv_bfloat16 l16 = __float2bfloat16(hnew - __bfloat162float(h16));
                    if (layer == 0) {
                        g_h1hi[(size_t)t * BB * HH + (size_t)b * HH + jb] = h16;
                        g_h1lo[(size_t)t * BB * HH + (size_t)b * HH + jb] = l16;
                    } else if (t == TT - 1) {
                        g_h2[(size_t)jb * BB + b] = hnew;
                    }
                    g_hhi[t & 1][(size_t)b * HH + jb] = h16;
                    g_hlo[t & 1][(size_t)b * HH + jb] = l16;
                }
            }
        }

        // ---- global barrier ----
        if (t < TT - 1) {
            __threadfence();
            __syncthreads();
            if (tid == 0) {
                atomicAdd(&g_bar[t], 1);
                while (*(volatile int*)(g_bar + t) < NCTA) { }
            }
            __syncthreads();
        }
    }
}

// ---- xg1 = h1 @ Wih1^T + bias : VERBATIM clone of the recurrence matmul ----
// grid (128 cb, 4 t-slices); CTA cb owns gate cols j = gate*HH + cb*8 + c.
// A = layer0 history split planes at [t][b][k]; B = Wih1 slice, smem-resident.
__global__ __launch_bounds__(256) void xg1_tc(
    const float* __restrict__ Wih,
    const float* __restrict__ bih, const float* __restrict__ bhh)
{
    extern __shared__ char smem[];
    const int tid  = threadIdx.x;
    const int cb   = blockIdx.x;
    const int wid  = tid >> 5;
    const int lane = tid & 31;
    const int g8   = lane >> 2;
    const int tg   = lane & 3;
    const int bh   = wid & 1;
    const int ks   = wid >> 1;

    // stage split W slice (identical loop; Whh -> Wih)
    {
        u16* whi = (u16*)(smem + SM_WHI);
        u16* wlo = (u16*)(smem + SM_WLO);
        for (int i = tid; i < 32 * HH; i += 256) {
            int n = i >> 10, k = i & 1023;
            int j = (n >> 3) * HH + cb * 8 + (n & 7);
            float w = Wih[(size_t)j * HH + k];
            __nv_bfloat16 h16 = __float2bfloat16(w);
            __nv_bfloat16 l16 = __float2bfloat16(w - __bfloat162float(h16));
            whi[n * WPIT + k] = *(u16*)&h16;
            wlo[n * WPIT + k] = *(u16*)&l16;
        }
    }
    __syncthreads();

    // bias per lane (used by warps 0-1): bias[gate][q&1] for cc = tg*2 + (q&1)
    float bias[4][2];
    #pragma unroll
    for (int gate = 0; gate < 4; gate++)
        #pragma unroll
        for (int c01 = 0; c01 < 2; c01++) {
            int j = gate * HH + cb * 8 + tg * 2 + c01;
            bias[gate][c01] = bih[j] + bhh[j];
        }

    const int t0 = blockIdx.y * (TT / 4);
    for (int t = t0; t < t0 + TT / 4; t++) {
        const __nv_bfloat16* shi = g_h1hi + (size_t)t * BB * HH;
        const __nv_bfloat16* slo = g_h1lo + (size_t)t * BB * HH;

        float acc[2][4][4];
        #pragma unroll
        for (int rb = 0; rb < 2; rb++)
            #pragma unroll
            for (int nt = 0; nt < 4; nt++)
                #pragma unroll
                for (int q = 0; q < 4; q++) acc[rb][nt][q] = 0.0f;

        uint4 pf[2][4];
        #pragma unroll
        for (int q = 0; q < 4; q++) {
            int idx = q * 256 + tid;
            int row = idx >> 4, kq = idx & 15;
            size_t off = (size_t)row * HH + kq * 8;
            pf[0][q] = __ldcg((const uint4*)(shi + off));
            pf[1][q] = __ldcg((const uint4*)(slo + off));
        }

        for (int c = 0; c < 8; c++) {
            char* hbuf = smem + SM_H + (c & 1) * 2 * HPLANE;
            #pragma unroll
            for (int q = 0; q < 4; q++) {
                int idx = q * 256 + tid;
                int row = idx >> 4, kq = idx & 15;
                *(uint4*)(hbuf + row * (HPIT * 2) + kq * 16) = pf[0][q];
                *(uint4*)(hbuf + HPLANE + row * (HPIT * 2) + kq * 16) = pf[1][q];
            }
            __syncthreads();

            if (c < 7) {
                #pragma unroll
                for (int q = 0; q < 4; q++) {
                    int idx = q * 256 + tid;
                    int row = idx >> 4, kq = idx & 15;
                    size_t off = (size_t)row * HH + (c + 1) * 128 + kq * 8;
                    pf[0][q] = __ldcg((const uint4*)(shi + off));
                    pf[1][q] = __ldcg((const uint4*)(slo + off));
                }
            }

            const u16* hhi = (const u16*)hbuf;
            const u16* hlo = (const u16*)(hbuf + HPLANE);
            const u16* whi = (const u16*)(smem + SM_WHI);
            const u16* wlo = (const u16*)(smem + SM_WLO);

            #pragma unroll
            for (int kst = 0; kst < 2; kst++) {
                const int kk = ks * 32 + kst * 16;
                const int kg = c * 128 + kk;
                u32 Ahi[2][4], Alo[2][4], Bhi[4][2], Blo[4][2];
                #pragma unroll
                for (int rb = 0; rb < 2; rb++) {
                    const u16* p = hhi + (bh * 32 + rb * 16 + g8) * HPIT + kk + tg * 2;
                    Ahi[rb][0] = *(const u32*)p;
                    Ahi[rb][1] = *(const u32*)(p + 8 * HPIT);
                    Ahi[rb][2] = *(const u32*)(p + 8);
                    Ahi[rb][3] = *(const u32*)(p + 8 * HPIT + 8);
                    const u16* pl = hlo + (bh * 32 + rb * 16 + g8) * HPIT + kk + tg * 2;
                    Alo[rb][0] = *(const u32*)pl;
                    Alo[rb][1] = *(const u32*)(pl + 8 * HPIT);
                    Alo[rb][2] = *(const u32*)(pl + 8);
                    Alo[rb][3] = *(const u32*)(pl + 8 * HPIT + 8);
                }
                #pragma unroll
                for (int nt = 0; nt < 4; nt++) {
                    const u16* p = whi + (nt * 8 + g8) * WPIT + kg + tg * 2;
                    Bhi[nt][0] = *(const u32*)p;
                    Bhi[nt][1] = *(const u32*)(p + 8);
                    const u16* pl = wlo + (nt * 8 + g8) * WPIT + kg + tg * 2;
                    Blo[nt][0] = *(const u32*)pl;
                    Blo[nt][1] = *(const u32*)(pl + 8);
                }
                #pragma unroll
                for (int rb = 0; rb < 2; rb++)
                    #pragma unroll
                    for (int nt = 0; nt < 4; nt++) {
                        mma16816(acc[rb][nt], Ahi[rb], Bhi[nt]);
                        mma16816(acc[rb][nt], Ahi[rb], Blo[nt]);
                        mma16816(acc[rb][nt], Alo[rb], Bhi[nt]);
                    }
            }
        }

        // single-round 4-way k-split reduction (identical slots)
        {
            float* red = (float*)(smem + SM_H);
            if (ks > 0) {
                int s = (ks - 1) * 2 + bh;
                #pragma unroll
                for (int rb = 0; rb < 2; rb++)
                    #pragma unroll
                    for (int nt = 0; nt < 4; nt++)
                        #pragma unroll
                        for (int q = 0; q < 4; q++)
                            red[(size_t)s * (32 * 33) + (rb * 16 + nt * 4 + q) * 33 + lane]
                                = acc[rb][nt][q];
            }
            __syncthreads();
            if (ks == 0) {
                #pragma unroll
                for (int s = 0; s < 3; s++)
                    #pragma unroll
                    for (int rb = 0; rb < 2; rb++)
                        #pragma unroll
                        for (int nt = 0; nt < 4; nt++)
                            #pragma unroll
                            for (int q = 0; q < 4; q++)
                                acc[rb][nt][q] +=
                                    red[(size_t)(s * 2 + bh) * (32 * 33)
                                        + (rb * 16 + nt * 4 + q) * 33 + lane];
            }
        }

        // epilogue: warps 0-1 write xg[t] (same addressing the recurrence reads)
        if (wid < 2) {
            float* xgw = g_xg + (size_t)t * G4 * BB;
            #pragma unroll
            for (int rb = 0; rb < 2; rb++) {
                #pragma unroll
                for (int q = 0; q < 4; q++) {
                    int b  = bh * 32 + rb * 16 + g8 + ((q >> 1) ? 8 : 0);
                    int cc = tg * 2 + (q & 1);
                    int jb = cb * 8 + cc;
                    #pragma unroll
                    for (int gate = 0; gate < 4; gate++)
                        xgw[(size_t)(gate * HH + jb) * BB + b]
                            = acc[rb][gate][q] + bias[gate][q & 1];
                }
            }
        }
        // order reduction-slot reads before next iteration's chunk-0 staging
        __syncthreads();
    }
}

// ---- head ----
__global__ __launch_bounds__(128) void head_kernel(
    const float* __restrict__ Wh, const float* __restrict__ bh, float* __restrict__ out)
{
    __shared__ float red[4];
    const int r = blockIdx.x, b = blockIdx.y;
    const int tid = threadIdx.x;

    float s = 0.0f;
    for (int k = tid; k < HH; k += 128) s += g_h2[(size_t)k * BB + b] * Wh[(size_t)r * HH + k];
    #pragma unroll
    for (int o = 16; o > 0; o >>= 1) s += __shfl_down_sync(0xFFFFFFFFu, s, o);
    if ((tid & 31) == 0) red[tid >> 5] = s;
    __syncthreads();
    if (tid == 0) out[b * HOR + r] = red[0] + red[1] + red[2] + red[3] + bh[r];
}

extern "C" void kernel_launch(void* const* d_in, const int* in_sizes, int n_in,
                              void* d_out, int out_size) {
    const float* x     = (const float*)d_in[0];
    const float* Wih0  = (const float*)d_in[1];
    const float* Whh0  = (const float*)d_in[2];
    const float* bih0  = (const float*)d_in[3];
    const float* bhh0  = (const float*)d_in[4];
    const float* Wih1  = (const float*)d_in[5];
    const float* Whh1  = (const float*)d_in[6];
    const float* bih1  = (const float*)d_in[7];
    const float* bhh1  = (const float*)d_in[8];
    const float* Whead = (const float*)d_in[9];
    const float* bhead = (const float*)d_in[10];
    float* out = (float*)d_out;

    static int configured = 0;
    if (!configured) {
        cudaFuncSetAttribute(lstm_layer_tc,
                             cudaFuncAttributeMaxDynamicSharedMemorySize, SMEM_TC);
        cudaFuncSetAttribute(xg1_tc,
                             cudaFuncAttributeMaxDynamicSharedMemorySize, SMEM_TC);
        configured = 1;
    }

    // layer 0
    zero_state<<<2, 256>>>();
    gemm0<<<dim3(G4 / 128, TT), 128>>>(x, Wih0, bih0, bhh0);
    lstm_layer_tc<<<NCTA, 256, SMEM_TC>>>(Whh0, 0);    // writes g_h1hi/lo history

    // layer 1
    xg1_tc<<<dim3(NCTA, 4), 256, SMEM_TC>>>(Wih1, bih1, bhh1);
    zero_state<<<2, 256>>>();
    lstm_layer_tc<<<NCTA, 256, SMEM_TC>>>(Whh1, 1);

    // head
    head_kernel<<<dim3(HOR, BB), 128>>>(Whead, bhead, out);
}